// round 6
// baseline (speedup 1.0000x reference)
#include <cuda_runtime.h>

#define SNE_H 1080
#define SNE_W 1920
#define SNE_HW (SNE_H * SNE_W)
#define BX 32
#define BYT 10                 // thread rows
#define ROWS (BYT * 2)         // pixel rows per block = 20; 1080 % 20 == 0
#define TX (BX + 2)            // 34
#define TY (ROWS + 2)          // 22
#define NTHR (BX * BYT)        // 320

__device__ __forceinline__ bool f_isnan(float x) {
    return (__float_as_uint(x) & 0x7fffffffu) > 0x7f800000u;
}
// true iff x finite and > 0 (x never negative where used)
__device__ __forceinline__ bool f_pos_finite(float x) {
    return (__float_as_uint(x) - 1u) < 0x7f7fffffu;
}
__device__ __forceinline__ float frcp_fast(float x) {   // 0 -> +inf, like 1/Z
    float r; asm("rcp.approx.f32 %0, %1;" : "=f"(r) : "f"(x)); return r;
}

__device__ __forceinline__ float4 make_px(int vv, int uu, float z0,
                                          float cx, float cy, float inv_fx) {
    float y = z0 * ((float)vv - cy) * inv_fx;
    const bool neg = (y <= 0.f);
    const float z = neg ? 0.f : z0;
    y = neg ? 0.f : y;
    const float x = z0 * ((float)uu - cx) * inv_fx;   // X not masked (matches ref)
    return make_float4(x, y, z, frcp_fast(z));
}

struct N3 { float x, y, z; };

// One pixel from a 3x3 float4 neighborhood held in registers.
// top[0..2], mid[0..2] (mid[1] = center), bot[0..2].
__device__ __forceinline__ N3 compute_px(const float4* top, const float4* mid,
                                         const float4* bot, float fx, float fy) {
    const float4 c = mid[1];

    const float nxt = fx * (mid[2].w - mid[0].w);
    const float nyt = fy * (bot[1].w - top[1].w);

    // cos(atan(t)+pi) = -1/sqrt(1+t^2), sin = -t/sqrt(1+t^2).
    // fminf clamp is safe: if t is NaN all 8 directions gate off => snz=0 =>
    // s=NaN => bad-path output (0,0,-1) independent of a,b.
    const float t = __fdividef(nyt, nxt);
    const float at = fminf(fabsf(t), 1e18f);
    const float rp = rsqrtf(fmaf(at, at, 1.f));
    const float a = -rp;
    const float b = -copysignf(at * rp, t);

    const float nn = fmaf(nxt, nxt, nyt * nyt);
    float S = 0.f, snz = 0.f;
#pragma unroll
    for (int k = 0; k < 8; ++k) {
        const float4 nb = (k < 3) ? top[k] : (k < 5) ? mid[(k - 3) * 2]
                                           : bot[k - 5];
        const float Xd = c.x - nb.x;
        const float Yd = c.y - nb.y;
        const float Zd = c.z - nb.z;
        const float nzi = __fdividef(fmaf(nxt, Xd, nyt * Yd), Zd);
        const float arg = fmaf(nzi, nzi, nn);
        // Gate equivalent to reference's per-component NaN masking:
        // arg pos-finite <=> rn=rsqrt(arg) pos-finite <=> all terms finite.
        if (f_pos_finite(arg)) {
            const float rn = rsqrtf(arg);
            S   += rn;
            snz  = fmaf(nzi, rn, snz);
        }
    }
    const float snx = nxt * S;
    const float sny = nyt * S;

    // theta = -atan(s): sin = -s/sqrt(1+s^2), cos = 1/sqrt(1+s^2).
    // Ternary clamp preserves NaN (s NaN must reach the bad path).
    const float s = __fdividef(fmaf(snx, a, sny * b), snz);
    float as_ = fabsf(s);
    as_ = (as_ > 1e18f) ? 1e18f : as_;
    const float rs = rsqrtf(fmaf(as_, as_, 1.f));
    const float st = -copysignf(as_ * rs, s);
    float nz = rs;
    float nx = st * a;
    float ny = st * b;

    const bool bad = f_isnan(nz);
    nx = bad ? 0.f : nx;
    ny = bad ? 0.f : ny;
    nz = bad ? -1.f : nz;
    const float sgn = (ny > 0.f) ? -1.f : 1.f;
    return { nx * sgn, ny * sgn, nz * sgn };
}

__global__ void __launch_bounds__(NTHR)
sne_kernel(const float* __restrict__ depth,
           const float* __restrict__ cam,
           float* __restrict__ out)
{
    __shared__ float4 tile[TY][TX];   // (X, Y, Z_masked, D=1/Z)

    const int tx = threadIdx.x, ty = threadIdx.y;
    const int tid = ty * BX + tx;
    const int bu = blockIdx.x * BX, bv = blockIdx.y * ROWS;

    const float fx = cam[0], cx = cam[2], fy = cam[4], cy = cam[5];
    const float inv_fx = frcp_fast(fx);

    // ---- Fill 34x22 tile (748 elems, 320 threads -> 3 rounds) ----
#pragma unroll
    for (int base = 0; base < TX * TY; base += NTHR) {
        const int i = base + tid;
        if (i < TX * TY) {
            const int lv = i / TX, lu = i - lv * TX;
            const int vv = bv + lv - 1, uu = bu + lu - 1;
            float4 t = make_float4(0.f, 0.f, 0.f, 0.f);
            if ((unsigned)vv < SNE_H && (unsigned)uu < SNE_W)
                t = make_px(vv, uu, __ldg(depth + vv * SNE_W + uu), cx, cy, inv_fx);
            tile[lv][lu] = t;
        }
    }
    __syncthreads();

    const int u = bu + tx;
    const int v0 = bv + 2 * ty;     // pixel A row; B = v0 + 1 (always in-bounds:
                                    // bv <= 1060, 2*ty <= 18 => v0+1 <= 1079)
    const int r0 = 2 * ty;          // tile row of A's top neighbor

    // 4 rows x 3 cols of float4, shared between the two vertical pixels.
    float4 R0[3], R1[3], R2[3], R3[3];
#pragma unroll
    for (int cix = 0; cix < 3; ++cix) {
        R0[cix] = tile[r0    ][tx + cix];
        R1[cix] = tile[r0 + 1][tx + cix];
        R2[cix] = tile[r0 + 2][tx + cix];
    }
    const N3 pA = compute_px(R0, R1, R2, fx, fy);
#pragma unroll
    for (int cix = 0; cix < 3; ++cix)
        R3[cix] = tile[r0 + 3][tx + cix];
    const N3 pB = compute_px(R1, R2, R3, fx, fy);

    {
        const int idx = v0 * SNE_W + u;
        out[idx]              = pA.x;
        out[SNE_HW + idx]     = pA.y;
        out[2 * SNE_HW + idx] = pA.z;
    }
    {
        const int idx = (v0 + 1) * SNE_W + u;
        out[idx]              = pB.x;
        out[SNE_HW + idx]     = pB.y;
        out[2 * SNE_HW + idx] = pB.z;
    }
}

extern "C" void kernel_launch(void* const* d_in, const int* in_sizes, int n_in,
                              void* d_out, int out_size) {
    const float* depth = (const float*)d_in[0];
    const float* cam   = (const float*)d_in[1];
    float* out = (float*)d_out;
    dim3 blk(BX, BYT);
    dim3 grd(SNE_W / BX, SNE_H / ROWS);   // 60 x 54, exact tiling
    sne_kernel<<<grd, blk>>>(depth, cam, out);
}